// round 4
// baseline (speedup 1.0000x reference)
#include <cuda_runtime.h>
#include <cstdint>
#include <cmath>

#define B_ 16384
#define D_ 4096
#define H_ 32
#define HD_ 128
#define EPSF 1e-5f

// ---------------- scratch (static device globals: allocation-free) ----------------
__device__ float g_g[(size_t)B_ * D_];   // gated input, tf32-rounded
__device__ float g_q[(size_t)B_ * D_];
__device__ float g_k[(size_t)B_ * D_];
__device__ float g_v[(size_t)B_ * D_];
__device__ float g_h[(size_t)B_ * D_];   // post-LN, tf32-rounded
__device__ float g_wbuf[4][(size_t)D_ * D_];  // tf32-rounded Wq,Wk,Wv,Wo
__device__ float g_xm[B_];
__device__ float g_ym[D_];
__device__ float g_colpart[64 * D_];
__device__ float g_gx[B_];
__device__ float g_gy[D_];
__device__ float g_stats[4];   // mu_x, denom_x, mu_y, denom_y

// ---------------- helpers ----------------
__device__ __forceinline__ float to_tf32(float x) {
    uint32_t u;
    asm("cvt.rna.tf32.f32 %0, %1;" : "=r"(u) : "f"(x));
    return __uint_as_float(u);
}

__device__ __forceinline__ void cp_async16(uint32_t smem_addr, const void* gptr) {
    asm volatile("cp.async.cg.shared.global [%0], [%1], 16;\n" :: "r"(smem_addr), "l"(gptr));
}

__device__ __forceinline__ void mma_tf32(float* c, const uint32_t* a, const uint32_t* b) {
    asm volatile(
        "mma.sync.aligned.m16n8k8.row.col.f32.tf32.tf32.f32 "
        "{%0,%1,%2,%3}, {%4,%5,%6,%7}, {%8,%9}, {%0,%1,%2,%3};\n"
        : "+f"(c[0]), "+f"(c[1]), "+f"(c[2]), "+f"(c[3])
        : "r"(a[0]), "r"(a[1]), "r"(a[2]), "r"(a[3]), "r"(b[0]), "r"(b[1]));
}

__device__ __forceinline__ float blockSum256(float v) {
    __shared__ float sh[8];
    int lane = threadIdx.x & 31, w = threadIdx.x >> 5;
    #pragma unroll
    for (int o = 16; o; o >>= 1) v += __shfl_xor_sync(0xffffffffu, v, o);
    if (lane == 0) sh[w] = v;
    __syncthreads();
    if (threadIdx.x < 8) {
        v = sh[threadIdx.x];
        #pragma unroll
        for (int o = 4; o; o >>= 1) v += __shfl_xor_sync(0xffu, v, o);
        if (threadIdx.x == 0) sh[0] = v;
    }
    __syncthreads();
    return sh[0];
}

// ---------------- stage A: means, stats, gates ----------------
__global__ void rowmean_k(const float* __restrict__ x) {
    int b = blockIdx.x;
    const float4* xr = (const float4*)(x + (size_t)b * D_);
    float s = 0.f;
    for (int i = threadIdx.x; i < D_ / 4; i += 256) {
        float4 v = xr[i];
        s += (v.x + v.y) + (v.z + v.w);
    }
    s = blockSum256(s);
    if (threadIdx.x == 0) g_xm[b] = s * (1.0f / D_);
}

__global__ void colsum_k(const float* __restrict__ x) {
    int col = blockIdx.x * 256 + threadIdx.x;
    int r0 = blockIdx.y * 256;
    float s = 0.f;
    #pragma unroll 4
    for (int r = r0; r < r0 + 256; r++) s += x[(size_t)r * D_ + col];
    g_colpart[blockIdx.y * D_ + col] = s;
}

__global__ void colfin_k() {
    int col = blockIdx.x * 256 + threadIdx.x;
    float s = 0.f;
    #pragma unroll
    for (int i = 0; i < 64; i++) s += g_colpart[i * D_ + col];
    g_ym[col] = s * (1.0f / B_);
}

// mean + (sqrt(var+eps)+eps) of (w*v + b) over n values; double accumulation
__global__ void stats_k(int sel, int n, const float* __restrict__ wp,
                        const float* __restrict__ bp, int off) {
    const float* v = sel ? g_ym : g_xm;
    float wv = *wp, bv = *bp;
    double s = 0.0, s2 = 0.0;
    for (int i = threadIdx.x; i < n; i += 1024) {
        double t = (double)(wv * v[i] + bv);
        s += t; s2 += t * t;
    }
    __shared__ double sa[32], sb[32];
    int lane = threadIdx.x & 31, w = threadIdx.x >> 5;
    #pragma unroll
    for (int o = 16; o; o >>= 1) {
        s  += __shfl_xor_sync(0xffffffffu, s,  o);
        s2 += __shfl_xor_sync(0xffffffffu, s2, o);
    }
    if (lane == 0) { sa[w] = s; sb[w] = s2; }
    __syncthreads();
    if (threadIdx.x == 0) {
        double S = 0.0, S2 = 0.0;
        for (int i = 0; i < 32; i++) { S += sa[i]; S2 += sb[i]; }
        double mu = S / n;
        double var = S2 / n - mu * mu;
        g_stats[off] = (float)mu;
        g_stats[off + 1] = (float)(sqrt(var + 1e-5) + 1e-5);
    }
}

__global__ void gxy_k(const float* __restrict__ wx, const float* __restrict__ bx,
                      const float* __restrict__ wy, const float* __restrict__ by) {
    int i = blockIdx.x * 256 + threadIdx.x;
    if (i < B_) {
        float t = ((*wx) * g_xm[i] + (*bx) - g_stats[0]) / g_stats[1];
        g_gx[i] = 1.f / (1.f + expf(-t));
    } else if (i < B_ + D_) {
        int j = i - B_;
        float t = ((*wy) * g_ym[j] + (*by) - g_stats[2]) / g_stats[3];
        g_gy[j] = 1.f / (1.f + expf(-t));
    }
}

// g = tf32(x * gx[b] * gy[d])
__global__ void gmul_k(const float* __restrict__ x) {
    size_t i = ((size_t)blockIdx.x * 256 + threadIdx.x) * 4;
    int b = (int)(i >> 12);
    int d = (int)(i & 4095);
    float gxv = g_gx[b];
    float4 xv = *(const float4*)(x + i);
    float4 gyv = *(const float4*)(g_gy + d);
    float4 o;
    o.x = to_tf32(xv.x * gxv * gyv.x);
    o.y = to_tf32(xv.y * gxv * gyv.y);
    o.z = to_tf32(xv.z * gxv * gyv.z);
    o.w = to_tf32(xv.w * gxv * gyv.w);
    *(float4*)(g_g + i) = o;
}

// round a DxD weight matrix to tf32 into g_wbuf[sel]
__global__ void cvtw_k(const float* __restrict__ in, int sel) {
    size_t i = ((size_t)blockIdx.x * 256 + threadIdx.x) * 4;
    float4 v = *(const float4*)(in + i);
    float4 o;
    o.x = to_tf32(v.x); o.y = to_tf32(v.y); o.z = to_tf32(v.z); o.w = to_tf32(v.w);
    *(float4*)(g_wbuf[sel] + i) = o;
}

// ---------------- GEMM: C[M,N] = A[M,K] @ W[N,K]^T + bias ----------------
// BM=BN=128, BK=16, 256 threads (8 warps as 4x2, warp tile 32x64), tf32 m16n8k8,
// 2-stage cp.async double buffering, smem row stride 20 floats (conflict-free frag LDS).
#define GEMM_ISSUE(t_, buf_)                                                       \
    do {                                                                           \
        size_t k0 = (size_t)(t_) * 16;                                             \
        uint32_t off = (uint32_t)(buf_) * (uint32_t)(128 * 20 * sizeof(float));    \
        cp_async16(sA0 + off, Ag + (size_t)lr * D_ + k0 + lc);                     \
        cp_async16(sA1 + off, Ag + (size_t)(lr + 64) * D_ + k0 + lc);              \
        cp_async16(sB0 + off, Wg + (size_t)lr * D_ + k0 + lc);                     \
        cp_async16(sB1 + off, Wg + (size_t)(lr + 64) * D_ + k0 + lc);              \
        asm volatile("cp.async.commit_group;\n" ::: "memory");                     \
    } while (0)

__global__ void __launch_bounds__(256, 2)
gemm_k(int asel, int wsel, const float* __restrict__ bias, int csel,
       float* __restrict__ dout) {
    __shared__ float As[2][128][20];
    __shared__ float Bs[2][128][20];

    const float* A = asel ? g_h : g_g;
    const float* W = g_wbuf[wsel];
    float* C = (csel == 0) ? g_q : (csel == 1) ? g_k : (csel == 2) ? g_v : dout;

    int tid = threadIdx.x;
    int bn = blockIdx.x, bm = blockIdx.y;
    int warp = tid >> 5, lane = tid & 31;
    int wm = warp >> 1, wn = warp & 1;

    const float* Ag = A + (size_t)bm * 128 * D_;
    const float* Wg = W + (size_t)bn * 128 * D_;
    int lr = tid >> 2;          // 0..63
    int lc = (tid & 3) * 4;     // 0,4,8,12

    uint32_t sA0 = (uint32_t)__cvta_generic_to_shared(&As[0][lr][lc]);
    uint32_t sA1 = (uint32_t)__cvta_generic_to_shared(&As[0][lr + 64][lc]);
    uint32_t sB0 = (uint32_t)__cvta_generic_to_shared(&Bs[0][lr][lc]);
    uint32_t sB1 = (uint32_t)__cvta_generic_to_shared(&Bs[0][lr + 64][lc]);

    float acc[2][8][4];
    #pragma unroll
    for (int i = 0; i < 2; i++)
        #pragma unroll
        for (int j = 0; j < 8; j++) {
            acc[i][j][0] = 0.f; acc[i][j][1] = 0.f;
            acc[i][j][2] = 0.f; acc[i][j][3] = 0.f;
        }

    GEMM_ISSUE(0, 0);
    const int T = D_ / 16;  // 256
    int arow = wm * 32 + (lane >> 2);
    int brow = wn * 64 + (lane >> 2);
    int kc = lane & 3;

    for (int t = 0; t < T; t++) {
        int buf = t & 1;
        if (t + 1 < T) {
            GEMM_ISSUE(t + 1, buf ^ 1);
            asm volatile("cp.async.wait_group 1;\n" ::: "memory");
        } else {
            asm volatile("cp.async.wait_group 0;\n" ::: "memory");
        }
        __syncthreads();

        #pragma unroll
        for (int ks = 0; ks < 2; ks++) {
            int k0 = ks * 8 + kc;
            uint32_t afr[2][4];
            #pragma unroll
            for (int mt = 0; mt < 2; mt++) {
                afr[mt][0] = __float_as_uint(As[buf][arow + mt * 16][k0]);
                afr[mt][1] = __float_as_uint(As[buf][arow + mt * 16 + 8][k0]);
                afr[mt][2] = __float_as_uint(As[buf][arow + mt * 16][k0 + 4]);
                afr[mt][3] = __float_as_uint(As[buf][arow + mt * 16 + 8][k0 + 4]);
            }
            uint32_t bfr[8][2];
            #pragma unroll
            for (int nt = 0; nt < 8; nt++) {
                bfr[nt][0] = __float_as_uint(Bs[buf][brow + nt * 8][k0]);
                bfr[nt][1] = __float_as_uint(Bs[buf][brow + nt * 8][k0 + 4]);
            }
            #pragma unroll
            for (int mt = 0; mt < 2; mt++)
                #pragma unroll
                for (int nt = 0; nt < 8; nt++)
                    mma_tf32(acc[mt][nt], afr[mt], bfr[nt]);
        }
        __syncthreads();
    }

    // epilogue: c0,c1 at (row, 2c), (row, 2c+1); c2,c3 at (row+8, ...)
    int crow = bm * 128 + wm * 32 + (lane >> 2);
    int ccol = bn * 128 + wn * 64 + (lane & 3) * 2;
    #pragma unroll
    for (int mt = 0; mt < 2; mt++) {
        #pragma unroll
        for (int nt = 0; nt < 8; nt++) {
            int r = crow + mt * 16;
            int c = ccol + nt * 8;
            float b0 = bias[c], b1 = bias[c + 1];
            C[(size_t)r * D_ + c]           = acc[mt][nt][0] + b0;
            C[(size_t)r * D_ + c + 1]       = acc[mt][nt][1] + b1;
            C[(size_t)(r + 8) * D_ + c]     = acc[mt][nt][2] + b0;
            C[(size_t)(r + 8) * D_ + c + 1] = acc[mt][nt][3] + b1;
        }
    }
}

// ---------------- per-row scalar attention + residual + LayerNorm ----------------
// one block per row; thread t owns elements [16t, 16t+16) (all inside head t/8)
__global__ void __launch_bounds__(256) attn_k(const float* __restrict__ gamma,
                                              const float* __restrict__ beta) {
    int b = blockIdx.x;
    int t = threadIdx.x;
    size_t base = (size_t)b * D_;
    const float4* q4 = (const float4*)(g_q + base);
    const float4* k4 = (const float4*)(g_k + base);
    const float4* v4 = (const float4*)(g_v + base);
    const float4* g4 = (const float4*)(g_g + base);

    __shared__ float s_sc[32];
    __shared__ float s_w[32];
    __shared__ float s_red[2][8];

    float dot = 0.f;
    #pragma unroll
    for (int i = 0; i < 4; i++) {
        float4 a = q4[t * 4 + i], c = k4[t * 4 + i];
        dot += a.x * c.x + a.y * c.y + a.z * c.z + a.w * c.w;
    }
    dot += __shfl_xor_sync(0xffffffffu, dot, 4);
    dot += __shfl_xor_sync(0xffffffffu, dot, 2);
    dot += __shfl_xor_sync(0xffffffffu, dot, 1);
    if ((t & 7) == 0) s_sc[t >> 3] = dot * 0.088388347648318447f;  // 1/sqrt(128)
    __syncthreads();

    if (t < 32) {
        float s = s_sc[t];
        float m = s;
        #pragma unroll
        for (int o = 16; o; o >>= 1) m = fmaxf(m, __shfl_xor_sync(0xffffffffu, m, o));
        float e = expf(s - m);
        float sum = e;
        #pragma unroll
        for (int o = 16; o; o >>= 1) sum += __shfl_xor_sync(0xffffffffu, sum, o);
        s_w[t] = e / sum;
    }
    __syncthreads();

    float wgt = s_w[t >> 3];
    float av[16];
    float sum = 0.f, sq = 0.f;
    #pragma unroll
    for (int i = 0; i < 4; i++) {
        float4 vv = v4[t * 4 + i], gv = g4[t * 4 + i];
        float a0 = wgt * vv.x + gv.x;
        float a1 = wgt * vv.y + gv.y;
        float a2 = wgt * vv.z + gv.z;
        float a3 = wgt * vv.w + gv.w;
        av[i * 4 + 0] = a0; av[i * 4 + 1] = a1; av[i * 4 + 2] = a2; av[i * 4 + 3] = a3;
        sum += (a0 + a1) + (a2 + a3);
        sq += a0 * a0 + a1 * a1 + a2 * a2 + a3 * a3;
    }

    int lane = t & 31, w = t >> 5;
    #pragma unroll
    for (int o = 16; o; o >>= 1) {
        sum += __shfl_xor_sync(0xffffffffu, sum, o);
        sq  += __shfl_xor_sync(0xffffffffu, sq,  o);
    }
    if (lane == 0) { s_red[0][w] = sum; s_red[1][w] = sq; }
    __syncthreads();
    float S = 0.f, S2 = 0.f;
    #pragma unroll
    for (int i = 0; i < 8; i++) { S += s_red[0][i]; S2 += s_red[1][i]; }
    float mean = S * (1.0f / D_);
    float var = S2 * (1.0f / D_) - mean * mean;
    float rstd = rsqrtf(var + EPSF);

    float4* h4 = (float4*)(g_h + base);
    const float4* gm4 = (const float4*)gamma;
    const float4* bt4 = (const float4*)beta;
    #pragma unroll
    for (int i = 0; i < 4; i++) {
        float4 gm = gm4[t * 4 + i], bt = bt4[t * 4 + i];
        float4 o;
        o.x = to_tf32((av[i * 4 + 0] - mean) * rstd * gm.x + bt.x);
        o.y = to_tf32((av[i * 4 + 1] - mean) * rstd * gm.y + bt.y);
        o.z = to_tf32((av[i * 4 + 2] - mean) * rstd * gm.z + bt.z);
        o.w = to_tf32((av[i * 4 + 3] - mean) * rstd * gm.w + bt.w);
        h4[t * 4 + i] = o;
    }
}

// ---------------- launch ----------------
extern "C" void kernel_launch(void* const* d_in, const int* in_sizes, int n_in,
                              void* d_out, int out_size) {
    (void)in_sizes; (void)n_in; (void)out_size;
    const float* x     = (const float*)d_in[0];
    const float* wx    = (const float*)d_in[1];
    const float* bx    = (const float*)d_in[2];
    const float* wy    = (const float*)d_in[3];
    const float* by    = (const float*)d_in[4];
    const float* Wq    = (const float*)d_in[5];
    const float* bq    = (const float*)d_in[6];
    const float* Wk    = (const float*)d_in[7];
    const float* bk    = (const float*)d_in[8];
    const float* Wv    = (const float*)d_in[9];
    const float* bv    = (const float*)d_in[10];
    const float* Wo    = (const float*)d_in[11];
    const float* bo    = (const float*)d_in[12];
    const float* gamma = (const float*)d_in[13];
    const float* beta  = (const float*)d_in[14];
    float* out = (float*)d_out;

    // GRA gates
    rowmean_k<<<B_, 256>>>(x);
    colsum_k<<<dim3(16, 64), 256>>>(x);
    colfin_k<<<16, 256>>>();
    stats_k<<<1, 1024>>>(0, B_, wx, bx, 0);
    stats_k<<<1, 1024>>>(1, D_, wy, by, 2);
    gxy_k<<<(B_ + D_) / 256, 256>>>(wx, bx, wy, by);
    gmul_k<<<(B_ * (D_ / 4)) / 256, 256>>>(x);

    // tf32-round weights
    int cvblocks = (D_ * (D_ / 4)) / 256;
    cvtw_k<<<cvblocks, 256>>>(Wq, 0);
    cvtw_k<<<cvblocks, 256>>>(Wk, 1);
    cvtw_k<<<cvblocks, 256>>>(Wv, 2);
    cvtw_k<<<cvblocks, 256>>>(Wo, 3);

    // Q, K, V projections
    dim3 gg(D_ / 128, B_ / 128);
    gemm_k<<<gg, 256>>>(0, 0, bq, 0, nullptr);
    gemm_k<<<gg, 256>>>(0, 1, bk, 1, nullptr);
    gemm_k<<<gg, 256>>>(0, 2, bv, 2, nullptr);

    // scalar attention + residual + LN (writes tf32-rounded h)
    attn_k<<<B_, 256>>>(gamma, beta);

    // output projection -> d_out
    gemm_k<<<gg, 256>>>(1, 3, bo, 3, out);
}

// round 9
// speedup vs baseline: 3.7173x; 3.7173x over previous
#include <cuda_runtime.h>
#include <cuda_fp16.h>
#include <cstdint>
#include <cmath>

#define B_ 16384
#define D_ 4096
#define EPSF 1e-5f

// ---------------- scratch (static device globals: allocation-free) ----------------
__device__ __half g_g16[(size_t)B_ * D_];
__device__ __half g_q16[(size_t)B_ * D_];
__device__ __half g_k16[(size_t)B_ * D_];
__device__ __half g_v16[(size_t)B_ * D_];
__device__ __half g_h16[(size_t)B_ * D_];
__device__ __half g_w16[4][(size_t)D_ * D_];
__device__ float g_xm[B_];
__device__ float g_ym[D_];
__device__ float g_colpart[64 * D_];
__device__ float g_gx[B_];
__device__ float g_gy[D_];
__device__ float g_stats[4];   // mu_x, denom_x, mu_y, denom_y

// ---------------- helpers ----------------
__device__ __forceinline__ uint32_t f16x2_pack(float lo, float hi) {
    uint32_t u;
    asm("cvt.rn.f16x2.f32 %0, %1, %2;" : "=r"(u) : "f"(hi), "f"(lo));
    return u;
}

__device__ __forceinline__ void cp_async16(uint32_t smem_addr, const void* gptr) {
    asm volatile("cp.async.cg.shared.global [%0], [%1], 16;\n" :: "r"(smem_addr), "l"(gptr));
}

__device__ __forceinline__ void ldsm_x4(uint32_t& r0, uint32_t& r1, uint32_t& r2,
                                        uint32_t& r3, uint32_t addr) {
    asm volatile("ldmatrix.sync.aligned.m8n8.x4.shared.b16 {%0,%1,%2,%3}, [%4];"
                 : "=r"(r0), "=r"(r1), "=r"(r2), "=r"(r3) : "r"(addr));
}

__device__ __forceinline__ void mma16816(float* c, const uint32_t* a, const uint32_t* b) {
    asm volatile(
        "mma.sync.aligned.m16n8k16.row.col.f32.f16.f16.f32 "
        "{%0,%1,%2,%3}, {%4,%5,%6,%7}, {%8,%9}, {%0,%1,%2,%3};\n"
        : "+f"(c[0]), "+f"(c[1]), "+f"(c[2]), "+f"(c[3])
        : "r"(a[0]), "r"(a[1]), "r"(a[2]), "r"(a[3]), "r"(b[0]), "r"(b[1]));
}

__device__ __forceinline__ float blockSum256(float v) {
    __shared__ float sh[8];
    int lane = threadIdx.x & 31, w = threadIdx.x >> 5;
    #pragma unroll
    for (int o = 16; o; o >>= 1) v += __shfl_xor_sync(0xffffffffu, v, o);
    if (lane == 0) sh[w] = v;
    __syncthreads();
    if (threadIdx.x < 8) {
        v = sh[threadIdx.x];
        #pragma unroll
        for (int o = 4; o; o >>= 1) v += __shfl_xor_sync(0xffu, v, o);
        if (threadIdx.x == 0) sh[0] = v;
    }
    __syncthreads();
    return sh[0];
}

// ---------------- K1: rowmean (blocks 0..16383) + colsum partials (16384..17407) ----
__global__ void means_k(const float* __restrict__ x) {
    if (blockIdx.x < B_) {
        int b = blockIdx.x;
        const float4* xr = (const float4*)(x + (size_t)b * D_);
        float s = 0.f;
        for (int i = threadIdx.x; i < D_ / 4; i += 256) {
            float4 v = xr[i];
            s += (v.x + v.y) + (v.z + v.w);
        }
        s = blockSum256(s);
        if (threadIdx.x == 0) g_xm[b] = s * (1.0f / D_);
    } else {
        int cid = blockIdx.x - B_;            // 0..1023
        int col = (cid & 15) * 256 + threadIdx.x;
        int r0 = (cid >> 4) * 256;
        float s = 0.f;
        #pragma unroll 4
        for (int r = r0; r < r0 + 256; r++) s += x[(size_t)r * D_ + col];
        g_colpart[(cid >> 4) * D_ + col] = s;
    }
}

// ---------------- K2: finish column means ----------------
__global__ void colfin_k() {
    int col = blockIdx.x * 256 + threadIdx.x;
    float s = 0.f;
    #pragma unroll
    for (int i = 0; i < 64; i++) s += g_colpart[i * D_ + col];
    g_ym[col] = s * (1.0f / B_);
}

// ---------------- K3: both myln stats in one launch (block 0: x, block 1: y) -------
__global__ void stats2_k(const float* __restrict__ wx, const float* __restrict__ bx,
                         const float* __restrict__ wy, const float* __restrict__ by) {
    int sel = blockIdx.x;
    const float* v = sel ? g_ym : g_xm;
    int n = sel ? D_ : B_;
    float wv = sel ? *wy : *wx;
    float bv = sel ? *by : *bx;
    double s = 0.0, s2 = 0.0;
    for (int i = threadIdx.x; i < n; i += 1024) {
        double t = (double)(wv * v[i] + bv);
        s += t; s2 += t * t;
    }
    __shared__ double sa[32], sb[32];
    int lane = threadIdx.x & 31, w = threadIdx.x >> 5;
    #pragma unroll
    for (int o = 16; o; o >>= 1) {
        s  += __shfl_xor_sync(0xffffffffu, s,  o);
        s2 += __shfl_xor_sync(0xffffffffu, s2, o);
    }
    if (lane == 0) { sa[w] = s; sb[w] = s2; }
    __syncthreads();
    if (threadIdx.x == 0) {
        double S = 0.0, S2 = 0.0;
        for (int i = 0; i < 32; i++) { S += sa[i]; S2 += sb[i]; }
        double mu = S / n;
        double var = S2 / n - mu * mu;
        g_stats[sel * 2]     = (float)mu;
        g_stats[sel * 2 + 1] = (float)(sqrt(var + 1e-5) + 1e-5);
    }
}

// ---------------- K4: gates ----------------
__global__ void gxy_k(const float* __restrict__ wx, const float* __restrict__ bx,
                      const float* __restrict__ wy, const float* __restrict__ by) {
    int i = blockIdx.x * 256 + threadIdx.x;
    if (i < B_) {
        float t = ((*wx) * g_xm[i] + (*bx) - g_stats[0]) / g_stats[1];
        g_gx[i] = 1.f / (1.f + expf(-t));
    } else if (i < B_ + D_) {
        int j = i - B_;
        float t = ((*wy) * g_ym[j] + (*by) - g_stats[2]) / g_stats[3];
        g_gy[j] = 1.f / (1.f + expf(-t));
    }
}

// ---------------- K5: fused g=fp16(x*gx*gy) + fp16 weight conversion ---------------
// blocks [0,32768): gmul (8 elems/thread); blocks [32768,65536): weight cvt
__global__ void prep16_k(const float* __restrict__ x,
                         const float* __restrict__ W0, const float* __restrict__ W1,
                         const float* __restrict__ W2, const float* __restrict__ W3) {
    if (blockIdx.x < 32768) {
        size_t i = ((size_t)blockIdx.x * 256 + threadIdx.x) * 8;
        int b = (int)(i >> 12);
        int d = (int)(i & 4095);
        float gxv = g_gx[b];
        float4 x0 = *(const float4*)(x + i), x1 = *(const float4*)(x + i + 4);
        float4 y0 = *(const float4*)(g_gy + d), y1 = *(const float4*)(g_gy + d + 4);
        uint4 o;
        o.x = f16x2_pack(x0.x * gxv * y0.x, x0.y * gxv * y0.y);
        o.y = f16x2_pack(x0.z * gxv * y0.z, x0.w * gxv * y0.w);
        o.z = f16x2_pack(x1.x * gxv * y1.x, x1.y * gxv * y1.y);
        o.w = f16x2_pack(x1.z * gxv * y1.z, x1.w * gxv * y1.w);
        *(uint4*)(g_g16 + i) = o;
    } else {
        int cid = blockIdx.x - 32768;         // 0..32767
        int sel = cid >> 13;                  // 8192 blocks per matrix
        const float* W = (sel == 0) ? W0 : (sel == 1) ? W1 : (sel == 2) ? W2 : W3;
        size_t i = ((size_t)(cid & 8191) * 256 + threadIdx.x) * 8;
        float4 a = *(const float4*)(W + i), b = *(const float4*)(W + i + 4);
        uint4 o;
        o.x = f16x2_pack(a.x, a.y);
        o.y = f16x2_pack(a.z, a.w);
        o.z = f16x2_pack(b.x, b.y);
        o.w = f16x2_pack(b.z, b.w);
        *(uint4*)(g_w16[sel] + i) = o;
    }
}

// ---------------- fp16 mma.sync GEMM: C[M,N] = A[M,K] @ W[N,K]^T + bias ------------
// CTA tile 128x128, BK=64 halves (128B rows, XOR swizzle), 3-stage cp.async,
// 256 threads = 8 warps (2m x 4n), warp tile 64x32, m16n8k16 via ldmatrix.x4.
#define NSTG      3
#define STG_BYTES 32768              // (128 + 128) rows * 128B
#define SMB_OFF   16384              // B tile offset within a stage
#define KT_       64                 // 4096 / 64

#define GEMM_DYNSMEM (NSTG * STG_BYTES + 512)

#define GEMM_ISSUE(it_)                                                          \
    do {                                                                         \
        uint32_t sb = ub + ((it_) % NSTG) * STG_BYTES;                           \
        uint32_t ko = (uint32_t)(it_) * 64;                                      \
        _Pragma("unroll")                                                        \
        for (int i = 0; i < 4; i++) cp_async16(sb + dst[i], Ag + srcoff[i] + ko);\
        _Pragma("unroll")                                                        \
        for (int i = 4; i < 8; i++) cp_async16(sb + dst[i], Wg + srcoff[i] + ko);\
        asm volatile("cp.async.commit_group;" ::: "memory");                     \
    } while (0)

#define LOAD_FRAGS(buf_, sb_, ks_)                                               \
    do {                                                                         \
        _Pragma("unroll")                                                        \
        for (int mt = 0; mt < 4; mt++) {                                         \
            uint32_t ad = (sb_) + aRow[mt] +                                     \
                          (((aRx[mt] ^ ((ks_) * 2 + a_cb)) & 7) << 4) +          \
                          (((ks_) * 2 + a_cb) & 8) * 16;                         \
            ldsm_x4(af[buf_][mt][0], af[buf_][mt][1],                            \
                    af[buf_][mt][2], af[buf_][mt][3], ad);                       \
        }                                                                        \
        _Pragma("unroll")                                                        \
        for (int p = 0; p < 2; p++) {                                            \
            uint32_t bd = (sb_) + SMB_OFF + bRow[p] +                            \
                          (((bRx[p] ^ ((ks_) * 2 + b_cb)) & 7) << 4) +           \
                          (((ks_) * 2 + b_cb) & 8) * 16;                         \
            ldsm_x4(bf[buf_][p * 2][0], bf[buf_][p * 2][1],                      \
                    bf[buf_][p * 2 + 1][0], bf[buf_][p * 2 + 1][1], bd);         \
        }                                                                        \
    } while (0)

__global__ void __launch_bounds__(256, 1)
gemm16_k(int asel, int wsel, const float* __restrict__ bias, int csel,
         float* __restrict__ dout) {
    extern __shared__ char sm[];
    uint32_t ub;
    asm("{ .reg .u64 t; cvta.to.shared.u64 t, %1; cvt.u32.u64 %0, t; }" : "=r"(ub) : "l"(sm));

    const __half* A = asel ? g_h16 : g_g16;
    const __half* W = g_w16[wsel];
    __half* Ch = (csel == 0) ? g_q16 : (csel == 1) ? g_k16 : (csel == 2) ? g_v16 : nullptr;

    int tid = threadIdx.x, warp = tid >> 5, lane = tid & 31;
    int bn = blockIdx.x, bm = blockIdx.y;
    int wm = warp >> 2, wn = warp & 3;

    float* sbias = (float*)(sm + NSTG * STG_BYTES);
    if (tid < 128) sbias[tid] = bias[bn * 128 + tid];

    const __half* Ag = A + (size_t)(bm * 128) * D_;
    const __half* Wg = W + (size_t)(bn * 128) * D_;

    // producer geometry: 2048 16B chunks/stage, 8 per thread (4 A, 4 B)
    uint32_t dst[8], srcoff[8];
    #pragma unroll
    for (int i = 0; i < 8; i++) {
        int c = i * 256 + tid;
        int isB = c >> 10;
        int r = (c & 1023) >> 3, kc = c & 7;
        uint32_t off = (uint32_t)r * 128 + kc * 16;
        dst[i] = (off ^ ((off >> 3) & 0x70)) + (isB ? SMB_OFF : 0);
        srcoff[i] = (uint32_t)r * D_ + kc * 8;   // in halves
    }

    // ldmatrix geometry
    int grp = lane >> 3, l7 = lane & 7;
    int a_r = ((grp & 1) << 3) + l7;     // row within m16 tile
    int a_cb = grp >> 1;                 // 0: k[0:8), 1: k[8:16)
    int b_r = ((grp & 2) << 2) + l7;     // row within n16 pair
    int b_cb = grp & 1;
    uint32_t aRow[4], aRx[4], bRow[2], bRx[2];
    #pragma unroll
    for (int mt = 0; mt < 4; mt++) {
        int rr = wm * 64 + mt * 16 + a_r;
        aRow[mt] = (uint32_t)rr * 128;
        aRx[mt] = rr & 7;
    }
    #pragma unroll
    for (int p = 0; p < 2; p++) {
        int rr = wn * 32 + p * 16 + b_r;
        bRow[p] = (uint32_t)rr * 128;
        bRx[p] = rr & 7;
    }

    float acc[4][4][4];
    #pragma unroll
    for (int mt = 0; mt < 4; mt++)
        #pragma unroll
        for (int nt = 0; nt < 4; nt++)
            #pragma unroll
            for (int e = 0; e < 4; e++) acc[mt][nt][e] = 0.f;

    __syncthreads();   // sbias written before any reuse; also orders nothing else

    GEMM_ISSUE(0);
    GEMM_ISSUE(1);

    uint32_t af[2][4][4], bf[2][4][2];

    for (int it = 0; it < KT_; ++it) {
        if (it + 2 < KT_) {
            GEMM_ISSUE(it + 2);
            asm volatile("cp.async.wait_group 2;" ::: "memory");
        } else if (it + 1 < KT_) {
            asm volatile("cp.async.wait_group 1;" ::: "memory");
        } else {
            asm volatile("cp.async.wait_group 0;" ::: "memory");
        }
        __syncthreads();

        uint32_t sb = ub + (it % NSTG) * STG_BYTES;
        LOAD_FRAGS(0, sb, 0);
        #pragma unroll
        for (int ks = 0; ks < 4; ks++) {
            if (ks < 3) LOAD_FRAGS((ks + 1) & 1, sb, ks + 1);
            int cur = ks & 1;
            #pragma unroll
            for (int mt = 0; mt < 4; mt++)
                #pragma unroll
                for (int nt = 0; nt < 4; nt++)
                    mma16816(acc[mt][nt], af[cur][mt], bf[cur][nt]);
        }
        __syncthreads();
    }

    // epilogue: thread t of warp holds c[row = base+lane/4 (+8)][col = base+2*(lane%4)]
    int lrow = lane >> 2, lcol = (lane & 3) * 2;
    #pragma unroll
    for (int mt = 0; mt < 4; mt++) {
        #pragma unroll
        for (int nt = 0; nt < 4; nt++) {
            int r0 = bm * 128 + wm * 64 + mt * 16 + lrow;
            int cl = wn * 32 + nt * 8 + lcol;           // local col in [0,128)
            int cg = bn * 128 + cl;
            float b0 = sbias[cl], b1 = sbias[cl + 1];
            float v00 = acc[mt][nt][0] + b0, v01 = acc[mt][nt][1] + b1;
            float v10 = acc[mt][nt][2] + b0, v11 = acc[mt][nt][3] + b1;
            if (Ch) {
                *(uint32_t*)(Ch + (size_t)r0 * D_ + cg)       = f16x2_pack(v00, v01);
                *(uint32_t*)(Ch + (size_t)(r0 + 8) * D_ + cg) = f16x2_pack(v10, v11);
            } else {
                *(float2*)(dout + (size_t)r0 * D_ + cg)       = make_float2(v00, v01);
                *(float2*)(dout + (size_t)(r0 + 8) * D_ + cg) = make_float2(v10, v11);
            }
        }
    }
}

// ---------------- per-row scalar attention + residual + LayerNorm (fp16 I/O) -------
__global__ void __launch_bounds__(256) attn16_k(const float* __restrict__ gamma,
                                                const float* __restrict__ beta) {
    int b = blockIdx.x;
    int t = threadIdx.x;
    size_t base = (size_t)b * D_;
    const uint4* q4 = (const uint4*)(g_q16 + base);
    const uint4* k4 = (const uint4*)(g_k16 + base);
    const uint4* v4 = (const uint4*)(g_v16 + base);
    const uint4* g4 = (const uint4*)(g_g16 + base);

    __shared__ float s_sc[32];
    __shared__ float s_w[32];
    __shared__ float s_red[2][8];

    float dot = 0.f;
    #pragma unroll
    for (int i = 0; i < 2; i++) {
        uint4 qa = q4[t * 2 + i], ka = k4[t * 2 + i];
        const __half2* qh = (const __half2*)&qa;
        const __half2* kh = (const __half2*)&ka;
        #pragma unroll
        for (int j = 0; j < 4; j++) {
            float2 a = __half22float2(qh[j]), c = __half22float2(kh[j]);
            dot += a.x * c.x + a.y * c.y;
        }
    }
    dot += __shfl_xor_sync(0xffffffffu, dot, 4);
    dot += __shfl_xor_sync(0xffffffffu, dot, 2);
    dot += __shfl_xor_sync(0xffffffffu, dot, 1);
    if ((t & 7) == 0) s_sc[t >> 3] = dot * 0.088388347648318447f;  // 1/sqrt(128)
    __syncthreads();

    if (t < 32) {
        float s = s_sc[t];
        float m = s;
        #pragma unroll
        for (int o = 16; o; o >>= 1) m = fmaxf(m, __shfl_xor_sync(0xffffffffu, m, o));
        float e = expf(s - m);
        float sum = e;
        #pragma unroll
        for (int o = 16; o; o >>= 1) sum += __shfl_xor_sync(0xffffffffu, sum, o);
        s_w[t] = e / sum;
    }
    __syncthreads();

    float wgt = s_w[t >> 3];
    float av[16];
    float sum = 0.f, sq = 0.f;
    #pragma unroll
    for (int i = 0; i < 2; i++) {
        uint4 vv = v4[t * 2 + i], gg = g4[t * 2 + i];
        const __half2* vh = (const __half2*)&vv;
        const __half2* gh = (const __half2*)&gg;
        #pragma unroll
        for (int j = 0; j < 4; j++) {
            float2 vf = __half22float2(vh[j]), gf = __half22float2(gh[j]);
            float a0 = wgt * vf.x + gf.x;
            float a1 = wgt * vf.y + gf.y;
            av[i * 8 + j * 2]     = a0;
            av[i * 8 + j * 2 + 1] = a1;
            sum += a0 + a1;
            sq += a0 * a0 + a1 * a1;
        }
    }

    int lane = t & 31, w = t >> 5;
    #pragma unroll
    for (int o = 16; o; o >>= 1) {
        sum += __shfl_xor_sync(0xffffffffu, sum, o);
        sq  += __shfl_xor_sync(0xffffffffu, sq,  o);
    }
    if (lane == 0) { s_red[0][w] = sum; s_red[1][w] = sq; }
    __syncthreads();
    float S = 0.f, S2 = 0.f;
    #pragma unroll
    for (int i = 0; i < 8; i++) { S += s_red[0][i]; S2 += s_red[1][i]; }
    float mean = S * (1.0f / D_);
    float var = S2 * (1.0f / D_) - mean * mean;
    float rstd = rsqrtf(var + EPSF);

    uint4* h4o = (uint4*)(g_h16 + base);
    const float4* gm4 = (const float4*)gamma;
    const float4* bt4 = (const float4*)beta;
    #pragma unroll
    for (int i = 0; i < 2; i++) {
        float4 ga = gm4[t * 4 + i * 2], gb = gm4[t * 4 + i * 2 + 1];
        float4 ba = bt4[t * 4 + i * 2], bb = bt4[t * 4 + i * 2 + 1];
        float n0 = (av[i * 8 + 0] - mean) * rstd * ga.x + ba.x;
        float n1 = (av[i * 8 + 1] - mean) * rstd * ga.y + ba.y;
        float n2 = (av[i * 8 + 2] - mean) * rstd * ga.z + ba.z;
        float n3 = (av[i * 8 + 3] - mean) * rstd * ga.w + ba.w;
        float n4 = (av[i * 8 + 4] - mean) * rstd * gb.x + bb.x;
        float n5 = (av[i * 8 + 5] - mean) * rstd * gb.y + bb.y;
        float n6 = (av[i * 8 + 6] - mean) * rstd * gb.z + bb.z;
        float n7 = (av[i * 8 + 7] - mean) * rstd * gb.w + bb.w;
        uint4 o;
        o.x = f16x2_pack(n0, n1);
        o.y = f16x2_pack(n2, n3);
        o.z = f16x2_pack(n4, n5);
        o.w = f16x2_pack(n6, n7);
        h4o[t * 2 + i] = o;
    }
}

// ---------------- launch ----------------
extern "C" void kernel_launch(void* const* d_in, const int* in_sizes, int n_in,
                              void* d_out, int out_size) {
    (void)in_sizes; (void)n_in; (void)out_size;
    const float* x     = (const float*)d_in[0];
    const float* wx    = (const float*)d_in[1];
    const float* bx    = (const float*)d_in[2];
    const float* wy    = (const float*)d_in[3];
    const float* by    = (const float*)d_in[4];
    const float* Wq    = (const float*)d_in[5];
    const float* bq    = (const float*)d_in[6];
    const float* Wk    = (const float*)d_in[7];
    const float* bk    = (const float*)d_in[8];
    const float* Wv    = (const float*)d_in[9];
    const float* bv    = (const float*)d_in[10];
    const float* Wo    = (const float*)d_in[11];
    const float* bo    = (const float*)d_in[12];
    const float* gamma = (const float*)d_in[13];
    const float* beta  = (const float*)d_in[14];
    float* out = (float*)d_out;

    cudaFuncSetAttribute(gemm16_k, cudaFuncAttributeMaxDynamicSharedMemorySize,
                         GEMM_DYNSMEM);

    // 5 prep launches (so ncu -s 5 profiles the first GEMM)
    means_k<<<B_ + 1024, 256>>>(x);                       // 1
    colfin_k<<<16, 256>>>();                              // 2
    stats2_k<<<2, 1024>>>(wx, bx, wy, by);                // 3
    gxy_k<<<(B_ + D_) / 256, 256>>>(wx, bx, wy, by);      // 4
    prep16_k<<<65536, 256>>>(x, Wq, Wk, Wv, Wo);          // 5

    // fp16 mma.sync GEMMs
    dim3 gg(D_ / 128, B_ / 128);
    gemm16_k<<<gg, 256, GEMM_DYNSMEM>>>(0, 0, bq, 0, nullptr);  // 6  Q
    gemm16_k<<<gg, 256, GEMM_DYNSMEM>>>(0, 1, bk, 1, nullptr);  // 7  K
    gemm16_k<<<gg, 256, GEMM_DYNSMEM>>>(0, 2, bv, 2, nullptr);  // 8  V

    attn16_k<<<B_, 256>>>(gamma, beta);                         // 9

    gemm16_k<<<gg, 256, GEMM_DYNSMEM>>>(1, 3, bo, 3, out);      // 10  output proj
}